// round 12
// baseline (speedup 1.0000x reference)
#include <cuda_runtime.h>
#include <cstdint>

// ---------------- problem constants ----------------
#define S  2048
#define E  1024
#define H  1024
#define V  32000
#define NB 256          // grid size; all co-resident (148 SMs x 2 CTAs)

// ---------------- device scratch (no allocs allowed) ----------------
__device__ __align__(16) float g_gates[4 * H];
__device__ __align__(16) float g_h[H];
__device__ __align__(16) float g_u[H];
__device__ __align__(16) float g_scores[S];
__device__ __align__(16) float g_context[E];
__device__ __align__(16) float g_xt[H];
__device__ __align__(16) float g_lp[NB];
__device__ unsigned g_cnt;                  // barrier arrival counter (self-resetting)
__device__ volatile unsigned g_gen;         // barrier generation (monotonic across replays)

__device__ __forceinline__ float sigf(float x) { return 1.0f / (1.0f + expf(-x)); }

__device__ __forceinline__ float warp_sum(float s) {
#pragma unroll
    for (int o = 16; o; o >>= 1) s += __shfl_xor_sync(0xFFFFFFFFu, s, o);
    return s;
}

// grid-wide barrier: safe because all NB blocks are co-resident.
__device__ __forceinline__ void grid_bar() {
    __syncthreads();
    if (threadIdx.x == 0) {
        __threadfence();
        unsigned g = g_gen;
        if (atomicAdd(&g_cnt, 1u) == NB - 1u) {
            atomicExch(&g_cnt, 0u);
            __threadfence();
            g_gen = g + 1u;
        } else {
            while (g_gen == g) {}
        }
        __threadfence();
    }
    __syncthreads();
}

__device__ __forceinline__ void mma_tf32(float* c, const uint32_t* a, uint32_t b0, uint32_t b1) {
    asm volatile(
        "mma.sync.aligned.m16n8k8.row.col.f32.tf32.tf32.f32 "
        "{%0,%1,%2,%3}, {%4,%5,%6,%7}, {%8,%9}, {%0,%1,%2,%3};\n"
        : "+f"(c[0]), "+f"(c[1]), "+f"(c[2]), "+f"(c[3])
        : "r"(a[0]), "r"(a[1]), "r"(a[2]), "r"(a[3]), "r"(b0), "r"(b1));
}

__device__ __forceinline__ void cp16(uint32_t dst_smem, const void* src) {
    asm volatile("cp.async.cg.shared.global [%0], [%1], 16;\n" :: "r"(dst_smem), "l"(src));
}
__device__ __forceinline__ void cp_commit() {
    asm volatile("cp.async.commit_group;\n");
}
template <int N>
__device__ __forceinline__ void cp_wait() {
    asm volatile("cp.async.wait_group %0;\n" :: "n"(N));
}

// 1024-length dot: warp covers with 8 float4 per lane
__device__ __forceinline__ float dot1024(const float4* __restrict__ w,
                                         const float4* __restrict__ x, int lane) {
    float s = 0.f;
#pragma unroll
    for (int q = 0; q < 8; q++) {
        int k = lane + 32 * q;
        float4 a = w[k]; float4 b = x[k];
        s += a.x * b.x + a.y * b.y + a.z * b.z + a.w * b.w;
    }
    return s;
}

// ---------------- GEMM tile params ----------------
#define BM 64
#define BN 128
#define BKC 32
#define PADK 36
#define NSTAGE 4
#define NKC (E / BKC)
#define STAGE_FLOATS ((BM + BN) * PADK)
#define ATT_SMEM_BYTES (NSTAGE * STAGE_FLOATS * 4)

// ================== THE single mega kernel ==================
__global__ void __launch_bounds__(256, 2)
k_all(const float* __restrict__ enc, const float* __restrict__ W_att,
      const float* __restrict__ W_ih, const float* __restrict__ b_ih,
      const float* __restrict__ W_hh, const float* __restrict__ b_hh,
      const float* __restrict__ last_ctx, const float* __restrict__ emb,
      const int* __restrict__ word, const float* __restrict__ h0,
      const float* __restrict__ c0, const float* __restrict__ b_att,
      const float* __restrict__ v,
      const float* __restrict__ W_ah, const float* __restrict__ b_ah,
      const float* __restrict__ W_out, const float* __restrict__ b_out,
      float* __restrict__ out) {
    extern __shared__ float smem_dyn[];
    __shared__ float sacc[BM];
    __shared__ float sred[8];
    __shared__ float red2[256];
    __shared__ float sw[64];

    int bid  = blockIdx.x;
    int tid  = threadIdx.x;
    int wid  = tid >> 5;
    int lane = tid & 31;

    // ---------- phase 1: LSTM gates (4096 rows, 16 per block, 2 per warp) ----------
    {
        const float4* xe4 = (const float4*)(emb + (size_t)word[0] * E);
        const float4* lc4 = (const float4*)last_ctx;
        const float4* h04 = (const float4*)h0;
#pragma unroll
        for (int sub = 0; sub < 2; sub++) {
            int r = bid * 16 + wid * 2 + sub;
            const float4* wi4 = (const float4*)(W_ih + (size_t)r * (E + H));
            const float4* wh4 = (const float4*)(W_hh + (size_t)r * H);
            float s = dot1024(wi4, lc4, lane)
                    + dot1024(wi4 + 256, xe4, lane)
                    + dot1024(wh4, h04, lane);
            s = warp_sum(s);
            if (lane == 0) g_gates[r] = s + b_ih[r] + b_hh[r];
        }
    }
    grid_bar();   // B1: gates complete

    // ---------- phase 2: cell + u (blocks 0..127) + zero scratch ----------
    if (bid < 128) {
        float* sh = smem_dyn;    // [H]
#pragma unroll
        for (int j = 0; j < 4; j++) {
            int t = tid + 256 * j;
            float ig = sigf(g_gates[t]);
            float fg = sigf(g_gates[H + t]);
            float gg = tanhf(g_gates[2 * H + t]);
            float og = sigf(g_gates[3 * H + t]);
            float c  = fg * c0[t] + ig * gg;
            float h  = og * tanhf(c);
            sh[t] = h;
            if (bid == 0) {
                g_h[t] = h;
                out[V + t]     = h;
                out[V + H + t] = c;
                g_context[t]   = 0.f;
            }
        }
        if (bid == 1) {
#pragma unroll
            for (int j = 0; j < 8; j++) g_scores[tid + 256 * j] = 0.f;
        }
        __syncthreads();
        int r = bid * 8 + wid;
        const float4* wa4 = (const float4*)(W_att + (size_t)r * (H + E));
        float s = dot1024(wa4, (const float4*)sh, lane);
        s = warp_sum(s);
        if (lane == 0) g_u[r] = s + b_att[r];
        __syncthreads();   // done with sh before gemm overwrites smem
    }
    // NOTE: no grid barrier here — gemm mainloop doesn't touch g_u/g_scores;
    // the pre-epilogue barrier (B2) covers them.

    // ---------- phase 3: attention GEMM (all 256 blocks; tile = (bid&31, bid>>5)) ----
    float acc[2][4][4];
    int warp_m = wid >> 2;
    int warp_n = wid & 3;
    int gid  = lane >> 2;
    int tid4 = lane & 3;
    int s0  = (bid & 31) * BM;
    int h0g = (bid >> 5) * BN;
    {
        uint32_t smem_u32;
        {
            uint64_t tmp;
            asm("cvta.to.shared.u64 %0, %1;" : "=l"(tmp) : "l"(smem_dyn));
            smem_u32 = (uint32_t)tmp;
        }
#pragma unroll
        for (int mt = 0; mt < 2; mt++)
#pragma unroll
            for (int nt = 0; nt < 4; nt++)
#pragma unroll
                for (int r = 0; r < 4; r++) acc[mt][nt][r] = 0.f;

        int rA[2], cA[2], rB[4], cB[4];
#pragma unroll
        for (int i = 0; i < 2; i++) { int f = tid + 256 * i; rA[i] = f >> 3; cA[i] = f & 7; }
#pragma unroll
        for (int i = 0; i < 4; i++) { int f = tid + 256 * i; rB[i] = f >> 3; cB[i] = f & 7; }

        const float* encp = enc   + (size_t)s0 * E;
        const float* wap  = W_att + (size_t)h0g * (H + E) + H;

#define ISSUE(kc_) do {                                                             \
        int st_ = (kc_) & (NSTAGE - 1);                                             \
        uint32_t abase_ = smem_u32 + st_ * (STAGE_FLOATS * 4);                      \
        uint32_t bbase_ = abase_ + BM * PADK * 4;                                   \
        int kofs_ = (kc_) * BKC;                                                    \
        _Pragma("unroll")                                                           \
        for (int i = 0; i < 2; i++)                                                 \
            cp16(abase_ + (rA[i] * PADK + cA[i] * 4) * 4,                           \
                 encp + (size_t)rA[i] * E + kofs_ + cA[i] * 4);                     \
        _Pragma("unroll")                                                           \
        for (int i = 0; i < 4; i++)                                                 \
            cp16(bbase_ + (rB[i] * PADK + cB[i] * 4) * 4,                           \
                 wap + (size_t)rB[i] * (H + E) + kofs_ + cB[i] * 4);                \
        cp_commit();                                                                \
    } while (0)

        ISSUE(0); ISSUE(1); ISSUE(2);

        for (int kc = 0; kc < NKC; kc++) {
            cp_wait<2>();
            __syncthreads();
            if (kc + 3 < NKC) ISSUE(kc + 3);

            int st = kc & (NSTAGE - 1);
            const uint32_t* As_s = (const uint32_t*)(smem_dyn + st * STAGE_FLOATS);
            const uint32_t* Bs_s = As_s + BM * PADK;

#pragma unroll
            for (int ks = 0; ks < BKC / 8; ks++) {
                int kb = ks * 8;
                uint32_t af[2][4];
#pragma unroll
                for (int mt = 0; mt < 2; mt++) {
                    int row = warp_m * 32 + mt * 16 + gid;
                    af[mt][0] = As_s[row * PADK + kb + tid4];
                    af[mt][1] = As_s[(row + 8) * PADK + kb + tid4];
                    af[mt][2] = As_s[row * PADK + kb + tid4 + 4];
                    af[mt][3] = As_s[(row + 8) * PADK + kb + tid4 + 4];
                }
#pragma unroll
                for (int nt = 0; nt < 4; nt++) {
                    int col = warp_n * 32 + nt * 8 + gid;
                    uint32_t b0 = Bs_s[col * PADK + kb + tid4];
                    uint32_t b1 = Bs_s[col * PADK + kb + tid4 + 4];
#pragma unroll
                    for (int mt = 0; mt < 2; mt++)
                        mma_tf32(acc[mt][nt], af[mt], b0, b1);
                }
            }
        }
#undef ISSUE
    }

    grid_bar();   // B2: g_u ready + g_scores zeroed (cell phase) before epilogue atomics

    // ---------- phase 4: fused score epilogue ----------
    {
        if (tid < BM) sacc[tid] = 0.f;
        __syncthreads();

        float uu[4][2], vv[4][2];
#pragma unroll
        for (int nt = 0; nt < 4; nt++) {
            int h = h0g + warp_n * 32 + nt * 8 + 2 * tid4;
            uu[nt][0] = g_u[h];     uu[nt][1] = g_u[h + 1];
            vv[nt][0] = v[h];       vv[nt][1] = v[h + 1];
        }
#pragma unroll
        for (int mt = 0; mt < 2; mt++) {
            float r0 = 0.f, r1 = 0.f;
#pragma unroll
            for (int nt = 0; nt < 4; nt++) {
                r0 += vv[nt][0] * tanhf(acc[mt][nt][0] + uu[nt][0])
                    + vv[nt][1] * tanhf(acc[mt][nt][1] + uu[nt][1]);
                r1 += vv[nt][0] * tanhf(acc[mt][nt][2] + uu[nt][0])
                    + vv[nt][1] * tanhf(acc[mt][nt][3] + uu[nt][1]);
            }
            r0 += __shfl_xor_sync(0xFFFFFFFFu, r0, 1);
            r0 += __shfl_xor_sync(0xFFFFFFFFu, r0, 2);
            r1 += __shfl_xor_sync(0xFFFFFFFFu, r1, 1);
            r1 += __shfl_xor_sync(0xFFFFFFFFu, r1, 2);
            if (tid4 == 0) {
                atomicAdd(&sacc[warp_m * 32 + mt * 16 + gid], r0);
                atomicAdd(&sacc[warp_m * 32 + mt * 16 + gid + 8], r1);
            }
        }
        __syncthreads();
        if (tid < BM) atomicAdd(&g_scores[s0 + tid], sacc[tid]);
    }
    grid_bar();   // B3: scores complete

    // ---------- phase 5: softmax-denominator (redundant) + context ----------
    if (bid < 128) {
        float lsum = 0.f;
        for (int s = tid; s < S; s += 256) lsum += expf(g_scores[s]);
        red2[tid] = lsum; __syncthreads();
        for (int o = 128; o; o >>= 1) { if (tid < o) red2[tid] += red2[tid + o]; __syncthreads(); }
        float inv = 1.0f / red2[0];

        int e   = (bid & 3) * 256 + tid;
        int s0c = (bid >> 2) * 64;
        if (tid < 64) {
            float w = expf(g_scores[s0c + tid]) * inv;
            sw[tid] = w;
            if ((bid & 3) == 0) out[V + 3 * H + s0c + tid] = w;
        }
        __syncthreads();
        float accv = 0.f;
#pragma unroll 8
        for (int s = 0; s < 64; s++)
            accv += sw[s] * enc[(size_t)(s0c + s) * E + e];
        atomicAdd(&g_context[e], accv);
    }
    grid_bar();   // B4: context complete

    // ---------- phase 6: x_t ----------
    if (bid < 128) {
        int r = bid * 8 + wid;
        const float4* wa4 = (const float4*)(W_ah + (size_t)r * (E + H));
        float s = dot1024(wa4, (const float4*)g_context, lane)
                + dot1024(wa4 + 256, (const float4*)g_h, lane);
        s = warp_sum(s);
        if (lane == 0) {
            float xt = tanhf(s + b_ah[r]);
            g_xt[r] = xt;
            out[V + 2 * H + r] = xt;
        }
    }
    grid_bar();   // B5: x_t complete

    // ---------- phase 7: logits (persistent, 2048 warps stride V) ----------
    {
        const float4* x4 = (const float4*)g_xt;
        float esum = 0.f;
        for (int r = bid * 8 + wid; r < V; r += NB * 8) {
            const float4* w4 = (const float4*)(W_out + (size_t)r * H);
            float s = dot1024(w4, x4, lane);
            s = warp_sum(s);
            if (lane == 0) {
                float val = s + b_out[r];
                out[r] = val;
                esum += expf(val);
            }
        }
        if (lane == 0) sred[wid] = esum;
        __syncthreads();
        if (tid == 0) {
            float p = 0.f;
#pragma unroll
            for (int i = 0; i < 8; i++) p += sred[i];
            g_lp[bid] = p;
        }
    }
    grid_bar();   // B6: logits + partials complete

    // ---------- phase 8: log-softmax ----------
    {
        red2[tid] = g_lp[tid];   // NB == 256 == blockDim
        __syncthreads();
        for (int o = 128; o; o >>= 1) { if (tid < o) red2[tid] += red2[tid + o]; __syncthreads(); }
        float l = logf(red2[0]);
        int i = bid * 256 + tid;
        if (i < V) out[i] -= l;
    }
}

// ---------------- launch: ONE kernel, default stream, zero alloc ----------------
extern "C" void kernel_launch(void* const* d_in, const int* in_sizes, int n_in,
                              void* d_out, int out_size) {
    const float* enc      = (const float*)d_in[0];
    const int*   word     = (const int*)  d_in[1];
    const float* last_ctx = (const float*)d_in[2];
    const float* h0       = (const float*)d_in[3];
    const float* c0       = (const float*)d_in[4];
    const float* emb      = (const float*)d_in[5];
    const float* W_ih     = (const float*)d_in[6];
    const float* b_ih     = (const float*)d_in[7];
    const float* W_hh     = (const float*)d_in[8];
    const float* b_hh     = (const float*)d_in[9];
    const float* W_att    = (const float*)d_in[10];
    const float* b_att    = (const float*)d_in[11];
    const float* v        = (const float*)d_in[12];
    const float* W_ah     = (const float*)d_in[13];
    const float* b_ah     = (const float*)d_in[14];
    const float* W_out    = (const float*)d_in[15];
    const float* b_out    = (const float*)d_in[16];
    float* out = (float*)d_out;

    cudaFuncSetAttribute(k_all, cudaFuncAttributeMaxDynamicSharedMemorySize, ATT_SMEM_BYTES);

    k_all<<<NB, 256, ATT_SMEM_BYTES>>>(enc, W_att, W_ih, b_ih, W_hh, b_hh,
                                       last_ctx, emb, word, h0, c0, b_att, v,
                                       W_ah, b_ah, W_out, b_out, out);
}